// round 6
// baseline (speedup 1.0000x reference)
#include <cuda_runtime.h>
#include <cstdint>

// RecurrentCharLM: B=256, S=32, H=128, VOCAB=256, DEPTH=100, L=1.
// 128 blocks x 256 threads; block owns 2 batch rows; thread = (row, col).
// W column j in registers (128 regs/thread, duplicated across the 2 row-halves).
// 2 warps per SMSP so LDS latency / FFMA chains / BAR waits interleave.
// Inner product uses fma.rn.f32x2 (packed 2x fp32) with 4 accumulators.

#define BATCH 256
#define SEQ   32
#define HID   128
#define VOC   256
#define DEPTH_IT 100
#define NBLK  128
#define NTHR  256

typedef unsigned long long ull;

__device__ __forceinline__ ull pack2(float lo, float hi) {
    ull r; asm("mov.b64 %0, {%1,%2};" : "=l"(r) : "f"(lo), "f"(hi)); return r;
}
__device__ __forceinline__ void unpack2(ull v, float &lo, float &hi) {
    asm("mov.b64 {%0,%1}, %2;" : "=f"(lo), "=f"(hi) : "l"(v));
}
__device__ __forceinline__ ull fma2(ull a, ull b, ull c) {
    ull d; asm("fma.rn.f32x2 %0, %1, %2, %3;" : "=l"(d) : "l"(a), "l"(b), "l"(c));
    return d;
}
__device__ __forceinline__ ull add2(ull a, ull b) {
    ull d; asm("add.rn.f32x2 %0, %1, %2;" : "=l"(d) : "l"(a), "l"(b)); return d;
}
__device__ __forceinline__ ull d2u(double x) { return __double_as_longlong(x); }

__global__ void __launch_bounds__(NTHR, 1)
rnn_charlm_kernel(const int* __restrict__ chars,
                  const float* __restrict__ hidden,
                  const float* __restrict__ embed_w,
                  const float* __restrict__ Wg,      // (1,128,128): W[k][j]
                  const float* __restrict__ ro_w,    // (256,128)
                  const float* __restrict__ ro_b,    // (256,)
                  float* __restrict__ out, int out_size)
{
    // dynamic smem: ro_w in k-paired transposed layout
    // ro_p[(k>>1)*512 + 2*v + (k&1)] = ro_w[v][k]   (64*512 floats = 128KB)
    extern __shared__ float ro_p[];
    __shared__ __align__(16) float hs[2][2][HID];   // [buf][row][k]

    const int tid = threadIdx.x;
    const int j   = tid & 127;       // output column
    const int row = tid >> 7;        // 0 or 1
    const int r   = blockIdx.x * 2 + row;   // global batch row

    // ---- W column j into registers, packed along k: wq[m] = (W[2m][j], W[2m+1][j])
    ull wq[64];
#pragma unroll
    for (int m = 0; m < 64; ++m)
        wq[m] = pack2(Wg[(2 * m) * HID + j], Wg[(2 * m + 1) * HID + j]);

    // ---- stage ro_w into smem (coalesced global read, scattered smem write; once)
    for (int idx = tid; idx < VOC * HID; idx += NTHR) {
        int v = idx / HID, k = idx % HID;
        ro_p[(k >> 1) * 512 + 2 * v + (k & 1)] = ro_w[idx];
    }

    float h = hidden[r * HID + j];
    const float rb_lo = ro_b[j];
    const float rb_hi = ro_b[j + 128];
    __syncthreads();

    for (int t = 0; t < SEQ; ++t) {
        // embed add (h = h + emb_t)
        const int c = chars[r * SEQ + t];
        h += embed_w[c * HID + j];

        int cur = 0;
        hs[0][row][j] = h;
        __syncthreads();

        // ---- 100 chained relu(h @ W) iterations
        for (int it = 0; it < DEPTH_IT; ++it) {
            const double2* p = (const double2*)hs[cur][row];
            ull a0 = 0, a1 = 0, a2 = 0, a3 = 0;
#pragma unroll
            for (int q = 0; q < 32; q += 2) {       // 8 k per step
                double2 x = p[q];                   // k = 4q .. 4q+3
                double2 y = p[q + 1];               // k = 4q+4 .. 4q+7
                a0 = fma2(d2u(x.x), wq[2 * q],     a0);
                a1 = fma2(d2u(x.y), wq[2 * q + 1], a1);
                a2 = fma2(d2u(y.x), wq[2 * q + 2], a2);
                a3 = fma2(d2u(y.y), wq[2 * q + 3], a3);
            }
            ull s = add2(add2(a0, a1), add2(a2, a3));
            float lo, hi;
            unpack2(s, lo, hi);
            h = fmaxf(lo + hi, 0.0f);
            cur ^= 1;
            hs[cur][row][j] = h;
            __syncthreads();
        }

        // ---- readout: logits[r][v] for v = j and v = j+128
        {
            const double2* p = (const double2*)hs[cur][row];
            ull A0a = 0, A0b = 0, A1a = 0, A1b = 0;
#pragma unroll
            for (int q = 0; q < 32; ++q) {          // 2 k-pairs per q
                double2 x = p[q];
                const float* b0 = &ro_p[(2 * q) * 512];
                const float* b1 = &ro_p[(2 * q + 1) * 512];
                ull ra0 = *(const ull*)&b0[2 * j];
                ull rc0 = *(const ull*)&b0[256 + 2 * j];
                ull ra1 = *(const ull*)&b1[2 * j];
                ull rc1 = *(const ull*)&b1[256 + 2 * j];
                A0a = fma2(d2u(x.x), ra0, A0a);
                A1a = fma2(d2u(x.x), rc0, A1a);
                A0b = fma2(d2u(x.y), ra1, A0b);
                A1b = fma2(d2u(x.y), rc1, A1b);
            }
            float lo, hi;
            float* o = out + (r * SEQ + t) * VOC;
            ull A0 = add2(A0a, A0b);
            ull A1 = add2(A1a, A1b);
            unpack2(A0, lo, hi); o[j]       = lo + hi + rb_lo;
            unpack2(A1, lo, hi); o[j + 128] = lo + hi + rb_hi;
        }
        // protect hs[0] (written at next timestep start) from readers still in readout
        __syncthreads();
    }

    // ---- h_final (if the harness output includes it after the logits)
    if (out_size >= BATCH * SEQ * VOC + BATCH * HID) {
        float* hf = out + BATCH * SEQ * VOC;
        hf[r * HID + j] = h;
    }
}

extern "C" void kernel_launch(void* const* d_in, const int* in_sizes, int n_in,
                              void* d_out, int out_size)
{
    (void)in_sizes; (void)n_in;
    const int*   chars   = (const int*)d_in[0];
    const float* hidden  = (const float*)d_in[1];
    const float* embed_w = (const float*)d_in[2];
    const float* Ws      = (const float*)d_in[3];
    const float* ro_w    = (const float*)d_in[4];
    const float* ro_b    = (const float*)d_in[5];
    float* out = (float*)d_out;

    const size_t smem = 64 * 512 * sizeof(float);   // 128KB dynamic
    cudaFuncSetAttribute(rnn_charlm_kernel,
                         cudaFuncAttributeMaxDynamicSharedMemorySize, (int)smem);
    rnn_charlm_kernel<<<NBLK, NTHR, smem>>>(chars, hidden, embed_w, Ws,
                                            ro_w, ro_b, out, out_size);
}